// round 10
// baseline (speedup 1.0000x reference)
#include <cuda_runtime.h>
#include <math.h>

#define H 2048
#define V 50257
#define L 20

// Scratch (device globals: no allocation allowed in kernel_launch)
__device__ __align__(16) float g_sc[L];           // raw attention scores
__device__ __align__(16) float g_concat[2 * H];   // [embedded ; context]
__device__ __align__(16) float g_x[H];            // relu(comb) output
__device__ __align__(16) float g_hnew[H];         // new hidden

__device__ __forceinline__ float warp_reduce(float v) {
    #pragma unroll
    for (int o = 16; o > 0; o >>= 1)
        v += __shfl_xor_sync(0xFFFFFFFFu, v, o);
    return v;
}

__device__ __forceinline__ float dot4(float4 a, float4 b) {
    return a.x * b.x + a.y * b.y + a.z * b.z + a.w * b.w;
}

// ---------------------------------------------------------------------------
// K1a: attention scores. One CTA per l (20 CTAs, 256 threads).
// ---------------------------------------------------------------------------
__global__ void k1a_scores(const int* __restrict__ input_ids,
                           const float* __restrict__ hidden,
                           const float* __restrict__ emb,
                           const float* __restrict__ attn_w,
                           const float* __restrict__ attn_b)
{
    __shared__ float red[8];
    const int l   = blockIdx.x;
    const int tid = threadIdx.x;
    const int id  = input_ids[0];

    const float4* aw = reinterpret_cast<const float4*>(attn_w + l * (2 * H));
    const float4* e4 = reinterpret_cast<const float4*>(emb + (long long)id * H);
    const float4* h4 = reinterpret_cast<const float4*>(hidden);

    float s = 0.f;
    #pragma unroll
    for (int i = tid; i < 1024; i += 256) {
        float4 a = __ldcs(aw + i);
        float4 x = (i < 512) ? e4[i] : h4[i - 512];
        s += dot4(a, x);
    }
    s = warp_reduce(s);
    if ((tid & 31) == 0) red[tid >> 5] = s;
    __syncthreads();
    if (tid < 8) {
        float v = red[tid];
        #pragma unroll
        for (int o = 4; o > 0; o >>= 1) v += __shfl_xor_sync(0xFFu, v, o);
        if (tid == 0) g_sc[l] = v + attn_b[l];
    }
}

// ---------------------------------------------------------------------------
// K1b: softmax (redundant per CTA, 20 values) + context + concat vector.
// ---------------------------------------------------------------------------
__global__ void k1b_ctx(const int* __restrict__ input_ids,
                        const float* __restrict__ enc,
                        const float* __restrict__ emb,
                        float* __restrict__ out)
{
    __shared__ float sw[L];
    const int tid = threadIdx.x;

    if (tid == 0) {
        float m = g_sc[0];
        #pragma unroll
        for (int l = 1; l < L; l++) m = fmaxf(m, g_sc[l]);
        float s = 0.f;
        float e[L];
        #pragma unroll
        for (int l = 0; l < L; l++) { e[l] = __expf(g_sc[l] - m); s += e[l]; }
        float inv = 1.f / s;
        #pragma unroll
        for (int l = 0; l < L; l++) sw[l] = e[l] * inv;
    }
    __syncthreads();

    const int j = blockIdx.x * 128 + tid;
    float ctx = 0.f;
    #pragma unroll
    for (int l = 0; l < L; l++)
        ctx += sw[l] * enc[l * H + j];

    const int id = input_ids[0];
    g_concat[j]     = emb[(long long)id * H + j];
    g_concat[H + j] = ctx;

    if (blockIdx.x == 0 && tid < L) out[V + H + tid] = sw[tid];
}

// ---------------------------------------------------------------------------
// K2: comb GEMV only: x = relu(comb_w @ concat + comb_b).
// block = 128 (4 warps, one row each), grid = 512 -> fine-grained balance.
// ---------------------------------------------------------------------------
__global__ void __launch_bounds__(128) k2_comb(
    const float* __restrict__ comb_w, const float* __restrict__ comb_b)
{
    __shared__ float4 xs[1024];
    const int tid  = threadIdx.x;
    const int warp = tid >> 5;
    const int lane = tid & 31;

    for (int i = tid; i < 1024; i += 128)
        xs[i] = reinterpret_cast<const float4*>(g_concat)[i];
    __syncthreads();

    const int r = blockIdx.x * 4 + warp;
    const float4* w = reinterpret_cast<const float4*>(comb_w) + (long long)r * 1024;
    float s = 0.f;
    #pragma unroll 8
    for (int i = lane; i < 1024; i += 32)
        s += dot4(__ldcs(w + i), xs[i]);
    s = warp_reduce(s);
    if (lane == 0) g_x[r] = fmaxf(s + comb_b[r], 0.f);
}

// ---------------------------------------------------------------------------
// K3: fused gi + gh + GRU gates. block = 384 (12 warps = 2 k's x 6 rows:
// {gi_r, gi_z, gi_n, gh_r, gh_z, gh_n}), grid = 1024. Both x and hidden
// staged in shared; gate math done per-k by one thread. 100 MB streamed.
// ---------------------------------------------------------------------------
__global__ void __launch_bounds__(384) k3_gru(
    const float* __restrict__ w_ih, const float* __restrict__ b_ih,
    const float* __restrict__ w_hh, const float* __restrict__ b_hh,
    const float* __restrict__ hidden, float* __restrict__ out)
{
    __shared__ float4 xs[512];       // g_x
    __shared__ float4 hs[512];       // hidden
    __shared__ float s_g[2][6];
    const int tid  = threadIdx.x;
    const int warp = tid >> 5;
    const int lane = tid & 31;

    for (int i = tid; i < 512; i += 384) {
        xs[i] = reinterpret_cast<const float4*>(g_x)[i];
        hs[i] = reinterpret_cast<const float4*>(hidden)[i];
    }
    __syncthreads();

    const int kl   = warp / 6;            // 0..1
    const int sub  = warp - kl * 6;       // 0..5
    const int mat  = sub / 3;             // 0: w_ih vs x, 1: w_hh vs hidden
    const int gate = sub - mat * 3;       // 0..2
    const int k    = blockIdx.x * 2 + kl;
    const int row  = k + gate * H;

    const float4* w = reinterpret_cast<const float4*>(mat ? w_hh : w_ih)
                      + (long long)row * 512;
    const float4* x = mat ? hs : xs;
    float s = 0.f;
    #pragma unroll 8
    for (int i = lane; i < 512; i += 32)
        s += dot4(__ldcs(w + i), x[i]);
    s = warp_reduce(s);
    if (lane == 0) s_g[kl][sub] = s + (mat ? b_hh[row] : b_ih[row]);
    __syncthreads();

    if (tid < 2) {
        const int kk = blockIdx.x * 2 + tid;
        float i_r = s_g[tid][0], i_z = s_g[tid][1], i_n = s_g[tid][2];
        float h_r = s_g[tid][3], h_z = s_g[tid][4], h_n = s_g[tid][5];
        float rr = 1.f / (1.f + __expf(-(i_r + h_r)));
        float zz = 1.f / (1.f + __expf(-(i_z + h_z)));
        float nn = tanhf(i_n + rr * h_n);
        float h0 = reinterpret_cast<const float*>(hs)[kk];
        float hn = (1.f - zz) * nn + zz * h0;
        g_hnew[kk]  = hn;
        out[V + kk] = hn;
    }
}

// ---------------------------------------------------------------------------
// K4: logits = out_w @ h_new + out_b. x in shared, streaming weight loads,
// 4 rows per warp. grid = ceil(V/32), block = 256.
// ---------------------------------------------------------------------------
__global__ void __launch_bounds__(256) k4_logits(
    const float* __restrict__ out_w, const float* __restrict__ out_b,
    float* __restrict__ out)
{
    __shared__ float4 xs[512];
    const int tid  = threadIdx.x;
    const int warp = tid >> 5;
    const int lane = tid & 31;

    for (int i = tid; i < 512; i += 256)
        xs[i] = reinterpret_cast<const float4*>(g_hnew)[i];
    __syncthreads();

    const long long r0 = ((long long)blockIdx.x * 8 + warp) * 4;
    if (r0 >= V) return;

    if (r0 + 3 < V) {
        const float4* w0 = reinterpret_cast<const float4*>(out_w) + r0 * 512;
        const float4* w1 = w0 + 512;
        const float4* w2 = w0 + 1024;
        const float4* w3 = w0 + 1536;
        float s0 = 0.f, s1 = 0.f, s2 = 0.f, s3 = 0.f;
        #pragma unroll 4
        for (int i = lane; i < 512; i += 32) {
            float4 b = xs[i];
            s0 += dot4(__ldcs(w0 + i), b);
            s1 += dot4(__ldcs(w1 + i), b);
            s2 += dot4(__ldcs(w2 + i), b);
            s3 += dot4(__ldcs(w3 + i), b);
        }
        s0 = warp_reduce(s0);
        s1 = warp_reduce(s1);
        s2 = warp_reduce(s2);
        s3 = warp_reduce(s3);
        if (lane == 0) {
            out[r0]     = s0 + out_b[r0];
            out[r0 + 1] = s1 + out_b[r0 + 1];
            out[r0 + 2] = s2 + out_b[r0 + 2];
            out[r0 + 3] = s3 + out_b[r0 + 3];
        }
    } else {
        for (long long r = r0; r < V; r++) {
            const float4* w = reinterpret_cast<const float4*>(out_w) + r * 512;
            float s = 0.f;
            #pragma unroll 4
            for (int i = lane; i < 512; i += 32)
                s += dot4(__ldcs(w + i), xs[i]);
            s = warp_reduce(s);
            if (lane == 0) out[r] = s + out_b[r];
        }
    }
}

// ---------------------------------------------------------------------------
extern "C" void kernel_launch(void* const* d_in, const int* in_sizes, int n_in,
                              void* d_out, int out_size)
{
    const int*   input_ids = (const int*)  d_in[0];
    const float* hidden    = (const float*)d_in[1];
    const float* enc       = (const float*)d_in[2];
    const float* emb       = (const float*)d_in[3];
    const float* attn_w    = (const float*)d_in[4];
    const float* attn_b    = (const float*)d_in[5];
    const float* comb_w    = (const float*)d_in[6];
    const float* comb_b    = (const float*)d_in[7];
    const float* w_ih      = (const float*)d_in[8];
    const float* w_hh      = (const float*)d_in[9];
    const float* b_ih      = (const float*)d_in[10];
    const float* b_hh      = (const float*)d_in[11];
    const float* out_w     = (const float*)d_in[12];
    const float* out_b     = (const float*)d_in[13];
    float* out = (float*)d_out;

    k1a_scores<<<L, 256>>>(input_ids, hidden, emb, attn_w, attn_b);
    k1b_ctx<<<16, 128>>>(input_ids, enc, emb, out);
    k2_comb<<<512, 128>>>(comb_w, comb_b);
    k3_gru<<<1024, 384>>>(w_ih, b_ih, w_hh, b_hh, hidden, out);
    k4_logits<<<(V + 31) / 32, 256>>>(out_w, out_b, out);
}

// round 11
// speedup vs baseline: 1.0006x; 1.0006x over previous
#include <cuda_runtime.h>
#include <math.h>

#define H 2048
#define V 50257
#define L 20

// Scratch (device globals: no allocation allowed in kernel_launch)
__device__ __align__(16) float g_sc[L];           // raw attention scores
__device__ __align__(16) float g_concat[2 * H];   // [embedded ; context]
__device__ __align__(16) float g_x[H];            // relu(comb) output
__device__ __align__(16) float g_hnew[H];         // new hidden

__device__ __forceinline__ float warp_reduce(float v) {
    #pragma unroll
    for (int o = 16; o > 0; o >>= 1)
        v += __shfl_xor_sync(0xFFFFFFFFu, v, o);
    return v;
}

__device__ __forceinline__ float dot4(float4 a, float4 b) {
    return a.x * b.x + a.y * b.y + a.z * b.z + a.w * b.w;
}

// ---------------------------------------------------------------------------
// K1a: attention scores. One CTA per l (20 CTAs, 256 threads).
// ---------------------------------------------------------------------------
__global__ void k1a_scores(const int* __restrict__ input_ids,
                           const float* __restrict__ hidden,
                           const float* __restrict__ emb,
                           const float* __restrict__ attn_w,
                           const float* __restrict__ attn_b)
{
    __shared__ float red[8];
    const int l   = blockIdx.x;
    const int tid = threadIdx.x;
    const int id  = input_ids[0];

    const float4* aw = reinterpret_cast<const float4*>(attn_w + l * (2 * H));
    const float4* e4 = reinterpret_cast<const float4*>(emb + (long long)id * H);
    const float4* h4 = reinterpret_cast<const float4*>(hidden);

    float s = 0.f;
    #pragma unroll
    for (int i = tid; i < 1024; i += 256) {
        float4 a = __ldcs(aw + i);
        float4 x = (i < 512) ? e4[i] : h4[i - 512];
        s += dot4(a, x);
    }
    s = warp_reduce(s);
    if ((tid & 31) == 0) red[tid >> 5] = s;
    __syncthreads();
    if (tid < 8) {
        float v = red[tid];
        #pragma unroll
        for (int o = 4; o > 0; o >>= 1) v += __shfl_xor_sync(0xFFu, v, o);
        if (tid == 0) g_sc[l] = v + attn_b[l];
    }
}

// ---------------------------------------------------------------------------
// K1b: softmax (redundant per CTA, 20 values) + context + concat vector.
// ---------------------------------------------------------------------------
__global__ void k1b_ctx(const int* __restrict__ input_ids,
                        const float* __restrict__ enc,
                        const float* __restrict__ emb,
                        float* __restrict__ out)
{
    __shared__ float sw[L];
    const int tid = threadIdx.x;

    if (tid == 0) {
        float m = g_sc[0];
        #pragma unroll
        for (int l = 1; l < L; l++) m = fmaxf(m, g_sc[l]);
        float s = 0.f;
        float e[L];
        #pragma unroll
        for (int l = 0; l < L; l++) { e[l] = __expf(g_sc[l] - m); s += e[l]; }
        float inv = 1.f / s;
        #pragma unroll
        for (int l = 0; l < L; l++) sw[l] = e[l] * inv;
    }
    __syncthreads();

    const int j = blockIdx.x * 128 + tid;
    float ctx = 0.f;
    #pragma unroll
    for (int l = 0; l < L; l++)
        ctx += sw[l] * enc[l * H + j];

    const int id = input_ids[0];
    g_concat[j]     = emb[(long long)id * H + j];
    g_concat[H + j] = ctx;

    if (blockIdx.x == 0 && tid < L) out[V + H + tid] = sw[tid];
}

// ---------------------------------------------------------------------------
// K2: comb GEMV only: x = relu(comb_w @ concat + comb_b).
// block = 128 (4 warps, one row each), grid = 512 -> fine-grained balance.
// ---------------------------------------------------------------------------
__global__ void __launch_bounds__(128) k2_comb(
    const float* __restrict__ comb_w, const float* __restrict__ comb_b)
{
    __shared__ float4 xs[1024];
    const int tid  = threadIdx.x;
    const int warp = tid >> 5;
    const int lane = tid & 31;

    for (int i = tid; i < 1024; i += 128)
        xs[i] = reinterpret_cast<const float4*>(g_concat)[i];
    __syncthreads();

    const int r = blockIdx.x * 4 + warp;
    const float4* w = reinterpret_cast<const float4*>(comb_w) + (long long)r * 1024;
    float s = 0.f;
    #pragma unroll 8
    for (int i = lane; i < 1024; i += 32)
        s += dot4(__ldcs(w + i), xs[i]);
    s = warp_reduce(s);
    if (lane == 0) g_x[r] = fmaxf(s + comb_b[r], 0.f);
}

// ---------------------------------------------------------------------------
// K3: fused gi + gh + GRU gates. block = 384 (12 warps = 2 k's x 6 rows:
// {gi_r, gi_z, gi_n, gh_r, gh_z, gh_n}), grid = 1024. Both x and hidden
// staged in shared; gate math done per-k by one thread. 100 MB streamed.
// ---------------------------------------------------------------------------
__global__ void __launch_bounds__(384) k3_gru(
    const float* __restrict__ w_ih, const float* __restrict__ b_ih,
    const float* __restrict__ w_hh, const float* __restrict__ b_hh,
    const float* __restrict__ hidden, float* __restrict__ out)
{
    __shared__ float4 xs[512];       // g_x
    __shared__ float4 hs[512];       // hidden
    __shared__ float s_g[2][6];
    const int tid  = threadIdx.x;
    const int warp = tid >> 5;
    const int lane = tid & 31;

    for (int i = tid; i < 512; i += 384) {
        xs[i] = reinterpret_cast<const float4*>(g_x)[i];
        hs[i] = reinterpret_cast<const float4*>(hidden)[i];
    }
    __syncthreads();

    const int kl   = warp / 6;            // 0..1
    const int sub  = warp - kl * 6;       // 0..5
    const int mat  = sub / 3;             // 0: w_ih vs x, 1: w_hh vs hidden
    const int gate = sub - mat * 3;       // 0..2
    const int k    = blockIdx.x * 2 + kl;
    const int row  = k + gate * H;

    const float4* w = reinterpret_cast<const float4*>(mat ? w_hh : w_ih)
                      + (long long)row * 512;
    const float4* x = mat ? hs : xs;
    float s = 0.f;
    #pragma unroll 8
    for (int i = lane; i < 512; i += 32)
        s += dot4(__ldcs(w + i), x[i]);
    s = warp_reduce(s);
    if (lane == 0) s_g[kl][sub] = s + (mat ? b_hh[row] : b_ih[row]);
    __syncthreads();

    if (tid < 2) {
        const int kk = blockIdx.x * 2 + tid;
        float i_r = s_g[tid][0], i_z = s_g[tid][1], i_n = s_g[tid][2];
        float h_r = s_g[tid][3], h_z = s_g[tid][4], h_n = s_g[tid][5];
        float rr = 1.f / (1.f + __expf(-(i_r + h_r)));
        float zz = 1.f / (1.f + __expf(-(i_z + h_z)));
        float nn = tanhf(i_n + rr * h_n);
        float h0 = reinterpret_cast<const float*>(hs)[kk];
        float hn = (1.f - zz) * nn + zz * h0;
        g_hnew[kk]  = hn;
        out[V + kk] = hn;
    }
}

// ---------------------------------------------------------------------------
// K4: logits = out_w @ h_new + out_b. x in shared, streaming weight loads,
// 4 rows per warp. grid = ceil(V/32), block = 256.
// ---------------------------------------------------------------------------
__global__ void __launch_bounds__(256) k4_logits(
    const float* __restrict__ out_w, const float* __restrict__ out_b,
    float* __restrict__ out)
{
    __shared__ float4 xs[512];
    const int tid  = threadIdx.x;
    const int warp = tid >> 5;
    const int lane = tid & 31;

    for (int i = tid; i < 512; i += 256)
        xs[i] = reinterpret_cast<const float4*>(g_hnew)[i];
    __syncthreads();

    const long long r0 = ((long long)blockIdx.x * 8 + warp) * 4;
    if (r0 >= V) return;

    if (r0 + 3 < V) {
        const float4* w0 = reinterpret_cast<const float4*>(out_w) + r0 * 512;
        const float4* w1 = w0 + 512;
        const float4* w2 = w0 + 1024;
        const float4* w3 = w0 + 1536;
        float s0 = 0.f, s1 = 0.f, s2 = 0.f, s3 = 0.f;
        #pragma unroll 4
        for (int i = lane; i < 512; i += 32) {
            float4 b = xs[i];
            s0 += dot4(__ldcs(w0 + i), b);
            s1 += dot4(__ldcs(w1 + i), b);
            s2 += dot4(__ldcs(w2 + i), b);
            s3 += dot4(__ldcs(w3 + i), b);
        }
        s0 = warp_reduce(s0);
        s1 = warp_reduce(s1);
        s2 = warp_reduce(s2);
        s3 = warp_reduce(s3);
        if (lane == 0) {
            out[r0]     = s0 + out_b[r0];
            out[r0 + 1] = s1 + out_b[r0 + 1];
            out[r0 + 2] = s2 + out_b[r0 + 2];
            out[r0 + 3] = s3 + out_b[r0 + 3];
        }
    } else {
        for (long long r = r0; r < V; r++) {
            const float4* w = reinterpret_cast<const float4*>(out_w) + r * 512;
            float s = 0.f;
            #pragma unroll 4
            for (int i = lane; i < 512; i += 32)
                s += dot4(__ldcs(w + i), xs[i]);
            s = warp_reduce(s);
            if (lane == 0) out[r] = s + out_b[r];
        }
    }
}

// ---------------------------------------------------------------------------
extern "C" void kernel_launch(void* const* d_in, const int* in_sizes, int n_in,
                              void* d_out, int out_size)
{
    const int*   input_ids = (const int*)  d_in[0];
    const float* hidden    = (const float*)d_in[1];
    const float* enc       = (const float*)d_in[2];
    const float* emb       = (const float*)d_in[3];
    const float* attn_w    = (const float*)d_in[4];
    const float* attn_b    = (const float*)d_in[5];
    const float* comb_w    = (const float*)d_in[6];
    const float* comb_b    = (const float*)d_in[7];
    const float* w_ih      = (const float*)d_in[8];
    const float* w_hh      = (const float*)d_in[9];
    const float* b_ih      = (const float*)d_in[10];
    const float* b_hh      = (const float*)d_in[11];
    const float* out_w     = (const float*)d_in[12];
    const float* out_b     = (const float*)d_in[13];
    float* out = (float*)d_out;

    k1a_scores<<<L, 256>>>(input_ids, hidden, emb, attn_w, attn_b);
    k1b_ctx<<<16, 128>>>(input_ids, enc, emb, out);
    k2_comb<<<512, 128>>>(comb_w, comb_b);
    k3_gru<<<1024, 384>>>(w_ih, b_ih, w_hh, b_hh, hidden, out);
    k4_logits<<<(V + 31) / 32, 256>>>(out_w, out_b, out);
}

// round 12
// speedup vs baseline: 1.0461x; 1.0455x over previous
#include <cuda_runtime.h>
#include <math.h>

#define H 2048
#define V 50257
#define L 20

// Scratch (device globals: no allocation allowed in kernel_launch)
__device__ __align__(16) float g_sc[L];           // raw attention scores
__device__ __align__(16) float g_concat[2 * H];   // [embedded ; context]
__device__ __align__(16) float g_x[H];            // relu(comb) output
__device__ __align__(16) float g_hnew[H];         // new hidden

__device__ __forceinline__ float warp_reduce(float v) {
    #pragma unroll
    for (int o = 16; o > 0; o >>= 1)
        v += __shfl_xor_sync(0xFFFFFFFFu, v, o);
    return v;
}

__device__ __forceinline__ float dot4(float4 a, float4 b) {
    return a.x * b.x + a.y * b.y + a.z * b.z + a.w * b.w;
}

// ---------------------------------------------------------------------------
// K1a: attention scores. One CTA per l (20 CTAs, 256 threads).
// ---------------------------------------------------------------------------
__global__ void k1a_scores(const int* __restrict__ input_ids,
                           const float* __restrict__ hidden,
                           const float* __restrict__ emb,
                           const float* __restrict__ attn_w,
                           const float* __restrict__ attn_b)
{
    __shared__ float red[8];
    const int l   = blockIdx.x;
    const int tid = threadIdx.x;
    const int id  = input_ids[0];

    const float4* aw = reinterpret_cast<const float4*>(attn_w + l * (2 * H));
    const float4* e4 = reinterpret_cast<const float4*>(emb + (long long)id * H);
    const float4* h4 = reinterpret_cast<const float4*>(hidden);

    float s = 0.f;
    #pragma unroll
    for (int i = tid; i < 1024; i += 256) {
        float4 a = __ldcs(aw + i);
        float4 x = (i < 512) ? e4[i] : h4[i - 512];
        s += dot4(a, x);
    }
    s = warp_reduce(s);
    if ((tid & 31) == 0) red[tid >> 5] = s;
    __syncthreads();
    if (tid < 8) {
        float v = red[tid];
        #pragma unroll
        for (int o = 4; o > 0; o >>= 1) v += __shfl_xor_sync(0xFFu, v, o);
        if (tid == 0) g_sc[l] = v + attn_b[l];
    }
}

// ---------------------------------------------------------------------------
// K1b: softmax (redundant per CTA, 20 values) + context + concat vector.
// ---------------------------------------------------------------------------
__global__ void k1b_ctx(const int* __restrict__ input_ids,
                        const float* __restrict__ enc,
                        const float* __restrict__ emb,
                        float* __restrict__ out)
{
    __shared__ float sw[L];
    const int tid = threadIdx.x;

    if (tid == 0) {
        float m = g_sc[0];
        #pragma unroll
        for (int l = 1; l < L; l++) m = fmaxf(m, g_sc[l]);
        float s = 0.f;
        float e[L];
        #pragma unroll
        for (int l = 0; l < L; l++) { e[l] = __expf(g_sc[l] - m); s += e[l]; }
        float inv = 1.f / s;
        #pragma unroll
        for (int l = 0; l < L; l++) sw[l] = e[l] * inv;
    }
    __syncthreads();

    const int j = blockIdx.x * 128 + tid;
    float ctx = 0.f;
    #pragma unroll
    for (int l = 0; l < L; l++)
        ctx += sw[l] * enc[l * H + j];

    const int id = input_ids[0];
    g_concat[j]     = emb[(long long)id * H + j];
    g_concat[H + j] = ctx;

    if (blockIdx.x == 0 && tid < L) out[V + H + tid] = sw[tid];
}

// ---------------------------------------------------------------------------
// K2: comb GEMV: x = relu(comb_w @ concat + comb_b).
// block = 256 (8 warps, one 16KB row each), grid = 256 -> ~14 warps/SM.
// ---------------------------------------------------------------------------
__global__ void __launch_bounds__(256) k2_comb(
    const float* __restrict__ comb_w, const float* __restrict__ comb_b)
{
    __shared__ float4 xs[1024];
    const int tid  = threadIdx.x;
    const int warp = tid >> 5;
    const int lane = tid & 31;

    for (int i = tid; i < 1024; i += 256)
        xs[i] = reinterpret_cast<const float4*>(g_concat)[i];
    __syncthreads();

    const int r = blockIdx.x * 8 + warp;
    const float4* w = reinterpret_cast<const float4*>(comb_w) + (long long)r * 1024;
    float s = 0.f;
    #pragma unroll 8
    for (int i = lane; i < 1024; i += 32)
        s += dot4(__ldcs(w + i), xs[i]);
    s = warp_reduce(s);
    if (lane == 0) g_x[r] = fmaxf(s + comb_b[r], 0.f);
}

// ---------------------------------------------------------------------------
// K3: fused gi + gh + GRU gates. Each warp owns one (k, gate) pair and
// streams TWO rows interleaved: w_ih[row] vs xs AND w_hh[row] vs hs
// (MLP ~16 per warp). block = 384 (12 warps = 4 k's x 3 gates), grid = 512.
// ---------------------------------------------------------------------------
__global__ void __launch_bounds__(384) k3_gru(
    const float* __restrict__ w_ih, const float* __restrict__ b_ih,
    const float* __restrict__ w_hh, const float* __restrict__ b_hh,
    const float* __restrict__ hidden, float* __restrict__ out)
{
    __shared__ float4 xs[512];       // g_x
    __shared__ float4 hs[512];       // hidden
    __shared__ float s_i[4][3];
    __shared__ float s_h[4][3];
    const int tid  = threadIdx.x;
    const int warp = tid >> 5;
    const int lane = tid & 31;

    for (int i = tid; i < 512; i += 384) {
        xs[i] = reinterpret_cast<const float4*>(g_x)[i];
        hs[i] = reinterpret_cast<const float4*>(hidden)[i];
    }
    __syncthreads();

    const int kl   = warp / 3;            // 0..3
    const int gate = warp - kl * 3;       // 0..2
    const int k    = blockIdx.x * 4 + kl;
    const int row  = k + gate * H;

    const float4* wi = reinterpret_cast<const float4*>(w_ih) + (long long)row * 512;
    const float4* wh = reinterpret_cast<const float4*>(w_hh) + (long long)row * 512;
    float si = 0.f, sh = 0.f;
    #pragma unroll 8
    for (int i = lane; i < 512; i += 32) {
        si += dot4(__ldcs(wi + i), xs[i]);
        sh += dot4(__ldcs(wh + i), hs[i]);
    }
    si = warp_reduce(si);
    sh = warp_reduce(sh);
    if (lane == 0) {
        s_i[kl][gate] = si + b_ih[row];
        s_h[kl][gate] = sh + b_hh[row];
    }
    __syncthreads();

    if (tid < 4) {
        const int kk = blockIdx.x * 4 + tid;
        float i_r = s_i[tid][0], i_z = s_i[tid][1], i_n = s_i[tid][2];
        float h_r = s_h[tid][0], h_z = s_h[tid][1], h_n = s_h[tid][2];
        float rr = 1.f / (1.f + __expf(-(i_r + h_r)));
        float zz = 1.f / (1.f + __expf(-(i_z + h_z)));
        float nn = tanhf(i_n + rr * h_n);
        float h0 = reinterpret_cast<const float*>(hs)[kk];
        float hn = (1.f - zz) * nn + zz * h0;
        g_hnew[kk]  = hn;
        out[V + kk] = hn;
    }
}

// ---------------------------------------------------------------------------
// K4: logits = out_w @ h_new + out_b. x in shared, streaming weight loads,
// 2 rows per warp (the configuration from the 94.4us run).
// grid = ceil(V/16), block = 256.
// ---------------------------------------------------------------------------
__global__ void __launch_bounds__(256) k4_logits(
    const float* __restrict__ out_w, const float* __restrict__ out_b,
    float* __restrict__ out)
{
    __shared__ float4 xs[512];
    const int tid  = threadIdx.x;
    const int warp = tid >> 5;
    const int lane = tid & 31;

    for (int i = tid; i < 512; i += 256)
        xs[i] = reinterpret_cast<const float4*>(g_hnew)[i];
    __syncthreads();

    const long long r0 = ((long long)blockIdx.x * 8 + warp) * 2;
    if (r0 >= V) return;
    const bool two = (r0 + 1 < V);

    const float4* w0 = reinterpret_cast<const float4*>(out_w) + r0 * 512;
    const float4* w1 = w0 + (two ? 512 : 0);

    float s0 = 0.f, s1 = 0.f;
    #pragma unroll 8
    for (int i = lane; i < 512; i += 32) {
        float4 b = xs[i];
        s0 += dot4(__ldcs(w0 + i), b);
        s1 += dot4(__ldcs(w1 + i), b);
    }
    s0 = warp_reduce(s0);
    s1 = warp_reduce(s1);
    if (lane == 0) {
        out[r0] = s0 + out_b[r0];
        if (two) out[r0 + 1] = s1 + out_b[r0 + 1];
    }
}

// ---------------------------------------------------------------------------
extern "C" void kernel_launch(void* const* d_in, const int* in_sizes, int n_in,
                              void* d_out, int out_size)
{
    const int*   input_ids = (const int*)  d_in[0];
    const float* hidden    = (const float*)d_in[1];
    const float* enc       = (const float*)d_in[2];
    const float* emb       = (const float*)d_in[3];
    const float* attn_w    = (const float*)d_in[4];
    const float* attn_b    = (const float*)d_in[5];
    const float* comb_w    = (const float*)d_in[6];
    const float* comb_b    = (const float*)d_in[7];
    const float* w_ih      = (const float*)d_in[8];
    const float* w_hh      = (const float*)d_in[9];
    const float* b_ih      = (const float*)d_in[10];
    const float* b_hh      = (const float*)d_in[11];
    const float* out_w     = (const float*)d_in[12];
    const float* out_b     = (const float*)d_in[13];
    float* out = (float*)d_out;

    k1a_scores<<<L, 256>>>(input_ids, hidden, emb, attn_w, attn_b);
    k1b_ctx<<<16, 128>>>(input_ids, enc, emb, out);
    k2_comb<<<256, 256>>>(comb_w, comb_b);
    k3_gru<<<512, 384>>>(w_ih, b_ih, w_hh, b_hh, hidden, out);
    k4_logits<<<(V + 15) / 16, 256>>>(out_w, out_b, out);
}

// round 13
// speedup vs baseline: 1.1185x; 1.0692x over previous
#include <cuda_runtime.h>
#include <math.h>

#define H 2048
#define V 50257
#define L 20

// Programmatic dependent launch controls (sm_90+)
#define GDC_LAUNCH() asm volatile("griddepcontrol.launch_dependents;")
#define GDC_WAIT()   asm volatile("griddepcontrol.wait;" ::: "memory")

// Scratch (device globals: no allocation allowed in kernel_launch)
__device__ __align__(16) float g_sc[L];           // raw attention scores
__device__ __align__(16) float g_concat[2 * H];   // [embedded ; context]
__device__ __align__(16) float g_x[H];            // relu(comb) output
__device__ __align__(16) float g_gh[3 * H];       // w_hh @ h0 + b_hh
__device__ __align__(16) float g_hnew[H];         // new hidden

__device__ __forceinline__ float warp_reduce(float v) {
    #pragma unroll
    for (int o = 16; o > 0; o >>= 1)
        v += __shfl_xor_sync(0xFFFFFFFFu, v, o);
    return v;
}

__device__ __forceinline__ float dot4(float4 a, float4 b) {
    return a.x * b.x + a.y * b.y + a.z * b.z + a.w * b.w;
}

// ---------------------------------------------------------------------------
// K1a: attention scores. One CTA per l (20 CTAs, 256 threads).
// Depends only on inputs -> no wait.
// ---------------------------------------------------------------------------
__global__ void k1a_scores(const int* __restrict__ input_ids,
                           const float* __restrict__ hidden,
                           const float* __restrict__ emb,
                           const float* __restrict__ attn_w,
                           const float* __restrict__ attn_b)
{
    GDC_LAUNCH();
    __shared__ float red[8];
    const int l   = blockIdx.x;
    const int tid = threadIdx.x;
    const int id  = input_ids[0];

    const float4* aw = reinterpret_cast<const float4*>(attn_w + l * (2 * H));
    const float4* e4 = reinterpret_cast<const float4*>(emb + (long long)id * H);
    const float4* h4 = reinterpret_cast<const float4*>(hidden);

    float s = 0.f;
    #pragma unroll
    for (int i = tid; i < 1024; i += 256) {
        float4 a = __ldcs(aw + i);
        float4 x = (i < 512) ? e4[i] : h4[i - 512];
        s += dot4(a, x);
    }
    s = warp_reduce(s);
    if ((tid & 31) == 0) red[tid >> 5] = s;
    __syncthreads();
    if (tid < 8) {
        float v = red[tid];
        #pragma unroll
        for (int o = 4; o > 0; o >>= 1) v += __shfl_xor_sync(0xFFu, v, o);
        if (tid == 0) g_sc[l] = v + attn_b[l];
    }
}

// ---------------------------------------------------------------------------
// K1b: softmax (redundant per CTA, 20 values) + context + concat vector.
// Consumes g_sc (k1a) -> wait first.
// ---------------------------------------------------------------------------
__global__ void k1b_ctx(const int* __restrict__ input_ids,
                        const float* __restrict__ enc,
                        const float* __restrict__ emb,
                        float* __restrict__ out)
{
    GDC_LAUNCH();
    GDC_WAIT();
    __shared__ float sw[L];
    const int tid = threadIdx.x;

    if (tid == 0) {
        float m = g_sc[0];
        #pragma unroll
        for (int l = 1; l < L; l++) m = fmaxf(m, g_sc[l]);
        float s = 0.f;
        float e[L];
        #pragma unroll
        for (int l = 0; l < L; l++) { e[l] = __expf(g_sc[l] - m); s += e[l]; }
        float inv = 1.f / s;
        #pragma unroll
        for (int l = 0; l < L; l++) sw[l] = e[l] * inv;
    }
    __syncthreads();

    const int j = blockIdx.x * 128 + tid;
    float ctx = 0.f;
    #pragma unroll
    for (int l = 0; l < L; l++)
        ctx += sw[l] * enc[l * H + j];

    const int id = input_ids[0];
    g_concat[j]     = emb[(long long)id * H + j];
    g_concat[H + j] = ctx;

    if (blockIdx.x == 0 && tid < L) out[V + H + tid] = sw[tid];
}

// ---------------------------------------------------------------------------
// K2: fused comb GEMV (CTAs 0..255: rows of comb_w, len 4096, relu -> g_x)
//     and gh GEMV (CTAs 256..1023: rows of w_hh, len 2048 -> g_gh).
// gh branch depends ONLY on inputs -> NO wait: its 50 MB streams
// concurrently with k1a/k1b via the early programmatic launch.
// ---------------------------------------------------------------------------
__global__ void __launch_bounds__(256) k2_comb_gh(
    const float* __restrict__ comb_w, const float* __restrict__ comb_b,
    const float* __restrict__ w_hh,   const float* __restrict__ b_hh,
    const float* __restrict__ hidden)
{
    GDC_LAUNCH();
    __shared__ float4 xs[1024];
    const int tid  = threadIdx.x;
    const int warp = tid >> 5;
    const int lane = tid & 31;

    if (blockIdx.x < 256) {
        GDC_WAIT();                           // g_concat from k1b
        for (int i = tid; i < 1024; i += 256)
            xs[i] = reinterpret_cast<const float4*>(g_concat)[i];
        __syncthreads();

        const int r = blockIdx.x * 8 + warp;
        const float4* w = reinterpret_cast<const float4*>(comb_w) + (long long)r * 1024;
        float s = 0.f;
        #pragma unroll 8
        for (int i = lane; i < 1024; i += 32)
            s += dot4(__ldcs(w + i), xs[i]);
        s = warp_reduce(s);
        if (lane == 0) g_x[r] = fmaxf(s + comb_b[r], 0.f);
    } else {
        for (int i = tid; i < 512; i += 256)
            xs[i] = reinterpret_cast<const float4*>(hidden)[i];
        __syncthreads();

        const int r = (blockIdx.x - 256) * 8 + warp;      // 0..6143
        const float4* w = reinterpret_cast<const float4*>(w_hh) + (long long)r * 512;
        float s = 0.f;
        #pragma unroll 8
        for (int i = lane; i < 512; i += 32)
            s += dot4(__ldcs(w + i), xs[i]);
        s = warp_reduce(s);
        if (lane == 0) g_gh[r] = s + b_hh[r];
    }
}

// ---------------------------------------------------------------------------
// K3: gi GEMV + GRU gates (proven R9 shape). 768 threads (24 warps);
// warp w handles (k_local = w/3, gate = w%3). grid = 256.
// Consumes g_x + g_gh (k2) -> wait first.
// ---------------------------------------------------------------------------
__global__ void __launch_bounds__(768) k3_gru(
    const float* __restrict__ w_ih, const float* __restrict__ b_ih,
    const float* __restrict__ hidden, float* __restrict__ out)
{
    GDC_LAUNCH();
    GDC_WAIT();
    __shared__ float4 xs[512];
    __shared__ float s_gi[8][3];
    const int tid  = threadIdx.x;
    const int warp = tid >> 5;
    const int lane = tid & 31;

    for (int i = tid; i < 512; i += 768)
        xs[i] = reinterpret_cast<const float4*>(g_x)[i];
    __syncthreads();

    const int k_local = warp / 3;           // 0..7
    const int gate    = warp - k_local * 3; // 0..2
    const int k       = blockIdx.x * 8 + k_local;
    const int row     = k + gate * H;

    const float4* w = reinterpret_cast<const float4*>(w_ih) + (long long)row * 512;
    float s = 0.f;
    #pragma unroll 8
    for (int i = lane; i < 512; i += 32)
        s += dot4(__ldcs(w + i), xs[i]);
    s = warp_reduce(s);
    if (lane == 0) s_gi[k_local][gate] = s + b_ih[row];
    __syncthreads();

    if (tid < 8) {
        const int kk = blockIdx.x * 8 + tid;
        float i_r = s_gi[tid][0], i_z = s_gi[tid][1], i_n = s_gi[tid][2];
        float h_r = g_gh[kk], h_z = g_gh[kk + H], h_n = g_gh[kk + 2 * H];
        float rr = 1.f / (1.f + __expf(-(i_r + h_r)));
        float zz = 1.f / (1.f + __expf(-(i_z + h_z)));
        float nn = tanhf(i_n + rr * h_n);
        float h0 = hidden[kk];
        float hn = (1.f - zz) * nn + zz * h0;
        g_hnew[kk]  = hn;
        out[V + kk] = hn;
    }
}

// ---------------------------------------------------------------------------
// K4: logits = out_w @ h_new + out_b. x in shared, streaming weight loads,
// 2 rows per warp (proven 82% DRAM shape). Consumes g_hnew -> wait first;
// early-launched blocks fill SMs as k3 drains.
// ---------------------------------------------------------------------------
__global__ void __launch_bounds__(256) k4_logits(
    const float* __restrict__ out_w, const float* __restrict__ out_b,
    float* __restrict__ out)
{
    GDC_WAIT();
    __shared__ float4 xs[512];
    const int tid  = threadIdx.x;
    const int warp = tid >> 5;
    const int lane = tid & 31;

    for (int i = tid; i < 512; i += 256)
        xs[i] = reinterpret_cast<const float4*>(g_hnew)[i];
    __syncthreads();

    const long long r0 = ((long long)blockIdx.x * 8 + warp) * 2;
    if (r0 >= V) return;
    const bool two = (r0 + 1 < V);

    const float4* w0 = reinterpret_cast<const float4*>(out_w) + r0 * 512;
    const float4* w1 = w0 + (two ? 512 : 0);

    float s0 = 0.f, s1 = 0.f;
    #pragma unroll 8
    for (int i = lane; i < 512; i += 32) {
        float4 b = xs[i];
        s0 += dot4(__ldcs(w0 + i), b);
        s1 += dot4(__ldcs(w1 + i), b);
    }
    s0 = warp_reduce(s0);
    s1 = warp_reduce(s1);
    if (lane == 0) {
        out[r0] = s0 + out_b[r0];
        if (two) out[r0 + 1] = s1 + out_b[r0 + 1];
    }
}

// ---------------------------------------------------------------------------
extern "C" void kernel_launch(void* const* d_in, const int* in_sizes, int n_in,
                              void* d_out, int out_size)
{
    const int*   input_ids = (const int*)  d_in[0];
    const float* hidden    = (const float*)d_in[1];
    const float* enc       = (const float*)d_in[2];
    const float* emb       = (const float*)d_in[3];
    const float* attn_w    = (const float*)d_in[4];
    const float* attn_b    = (const float*)d_in[5];
    const float* comb_w    = (const float*)d_in[6];
    const float* comb_b    = (const float*)d_in[7];
    const float* w_ih      = (const float*)d_in[8];
    const float* w_hh      = (const float*)d_in[9];
    const float* b_ih      = (const float*)d_in[10];
    const float* b_hh      = (const float*)d_in[11];
    const float* out_w     = (const float*)d_in[12];
    const float* out_b     = (const float*)d_in[13];
    float* out = (float*)d_out;

    // First kernel: plain launch.
    k1a_scores<<<L, 256>>>(input_ids, hidden, emb, attn_w, attn_b);

    // Subsequent kernels: programmatic stream serialization (PDL).
    cudaLaunchAttribute attr[1];
    attr[0].id = cudaLaunchAttributeProgrammaticStreamSerialization;
    attr[0].val.programmaticStreamSerializationAllowed = 1;

    {
        cudaLaunchConfig_t cfg = {};
        cfg.gridDim = dim3(16); cfg.blockDim = dim3(128);
        cfg.attrs = attr; cfg.numAttrs = 1; cfg.stream = 0;
        cudaLaunchKernelEx(&cfg, k1b_ctx, input_ids, enc, emb, out);
    }
    {
        cudaLaunchConfig_t cfg = {};
        cfg.gridDim = dim3(1024); cfg.blockDim = dim3(256);
        cfg.attrs = attr; cfg.numAttrs = 1; cfg.stream = 0;
        cudaLaunchKernelEx(&cfg, k2_comb_gh, comb_w, comb_b, w_hh, b_hh, hidden);
    }
    {
        cudaLaunchConfig_t cfg = {};
        cfg.gridDim = dim3(256); cfg.blockDim = dim3(768);
        cfg.attrs = attr; cfg.numAttrs = 1; cfg.stream = 0;
        cudaLaunchKernelEx(&cfg, k3_gru, w_ih, b_ih, hidden, out);
    }
    {
        cudaLaunchConfig_t cfg = {};
        cfg.gridDim = dim3((V + 15) / 16); cfg.blockDim = dim3(256);
        cfg.attrs = attr; cfg.numAttrs = 1; cfg.stream = 0;
        cudaLaunchKernelEx(&cfg, k4_logits, out_w, out_b, out);
    }
}

// round 14
// speedup vs baseline: 1.1314x; 1.0115x over previous
#include <cuda_runtime.h>
#include <math.h>

#define H 2048
#define V 50257
#define L 20

// Programmatic dependent launch controls (sm_90+)
#define GDC_LAUNCH() asm volatile("griddepcontrol.launch_dependents;")
#define GDC_WAIT()   asm volatile("griddepcontrol.wait;" ::: "memory")

// Scratch (device globals: no allocation allowed in kernel_launch)
__device__ __align__(16) float g_sc[L];           // raw attention scores
__device__ __align__(16) float g_concat[2 * H];   // [embedded ; context]
__device__ __align__(16) float g_x[H];            // relu(comb) output
__device__ __align__(16) float g_gh[3 * H];       // w_hh @ h0 + b_hh
__device__ __align__(16) float g_hnew[H];         // new hidden

__device__ __forceinline__ float warp_reduce(float v) {
    #pragma unroll
    for (int o = 16; o > 0; o >>= 1)
        v += __shfl_xor_sync(0xFFFFFFFFu, v, o);
    return v;
}

__device__ __forceinline__ float dot4(float4 a, float4 b) {
    return a.x * b.x + a.y * b.y + a.z * b.z + a.w * b.w;
}

// ---------------------------------------------------------------------------
// K1a: attention scores. One CTA per l (20 CTAs, 256 threads). No wait.
// ---------------------------------------------------------------------------
__global__ void k1a_scores(const int* __restrict__ input_ids,
                           const float* __restrict__ hidden,
                           const float* __restrict__ emb,
                           const float* __restrict__ attn_w,
                           const float* __restrict__ attn_b)
{
    GDC_LAUNCH();
    __shared__ float red[8];
    const int l   = blockIdx.x;
    const int tid = threadIdx.x;
    const int id  = input_ids[0];

    const float4* aw = reinterpret_cast<const float4*>(attn_w + l * (2 * H));
    const float4* e4 = reinterpret_cast<const float4*>(emb + (long long)id * H);
    const float4* h4 = reinterpret_cast<const float4*>(hidden);

    float s = 0.f;
    #pragma unroll
    for (int i = tid; i < 1024; i += 256) {
        float4 a = __ldcs(aw + i);
        float4 x = (i < 512) ? e4[i] : h4[i - 512];
        s += dot4(a, x);
    }
    s = warp_reduce(s);
    if ((tid & 31) == 0) red[tid >> 5] = s;
    __syncthreads();
    if (tid < 8) {
        float v = red[tid];
        #pragma unroll
        for (int o = 4; o > 0; o >>= 1) v += __shfl_xor_sync(0xFFu, v, o);
        if (tid == 0) g_sc[l] = v + attn_b[l];
    }
}

// ---------------------------------------------------------------------------
// K1b: softmax + context + concat vector. Waits on k1a (g_sc).
// ---------------------------------------------------------------------------
__global__ void k1b_ctx(const int* __restrict__ input_ids,
                        const float* __restrict__ enc,
                        const float* __restrict__ emb,
                        float* __restrict__ out)
{
    GDC_LAUNCH();
    GDC_WAIT();
    __shared__ float sw[L];
    const int tid = threadIdx.x;

    if (tid == 0) {
        float m = g_sc[0];
        #pragma unroll
        for (int l = 1; l < L; l++) m = fmaxf(m, g_sc[l]);
        float s = 0.f;
        float e[L];
        #pragma unroll
        for (int l = 0; l < L; l++) { e[l] = __expf(g_sc[l] - m); s += e[l]; }
        float inv = 1.f / s;
        #pragma unroll
        for (int l = 0; l < L; l++) sw[l] = e[l] * inv;
    }
    __syncthreads();

    const int j = blockIdx.x * 128 + tid;
    float ctx = 0.f;
    #pragma unroll
    for (int l = 0; l < L; l++)
        ctx += sw[l] * enc[l * H + j];

    const int id = input_ids[0];
    g_concat[j]     = emb[(long long)id * H + j];
    g_concat[H + j] = ctx;

    if (blockIdx.x == 0 && tid < L) out[V + H + tid] = sw[tid];
}

// ---------------------------------------------------------------------------
// K2: gh GEMV in blocks 0..767 (NO dependency -> streams immediately),
//     comb GEMV in blocks 768..1023 (prefetches half its row into regs
//     BEFORE waiting on k1b's g_concat).
// ---------------------------------------------------------------------------
__global__ void __launch_bounds__(256) k2_comb_gh(
    const float* __restrict__ comb_w, const float* __restrict__ comb_b,
    const float* __restrict__ w_hh,   const float* __restrict__ b_hh,
    const float* __restrict__ hidden)
{
    GDC_LAUNCH();
    __shared__ float4 xs[1024];
    const int tid  = threadIdx.x;
    const int warp = tid >> 5;
    const int lane = tid & 31;

    if (blockIdx.x < 768) {
        // gh branch: depends only on inputs.
        for (int i = tid; i < 512; i += 256)
            xs[i] = reinterpret_cast<const float4*>(hidden)[i];
        __syncthreads();

        const int r = blockIdx.x * 8 + warp;              // 0..6143
        const float4* w = reinterpret_cast<const float4*>(w_hh) + (long long)r * 512;
        float s = 0.f;
        #pragma unroll 8
        for (int i = lane; i < 512; i += 32)
            s += dot4(__ldcs(w + i), xs[i]);
        s = warp_reduce(s);
        if (lane == 0) g_gh[r] = s + b_hh[r];
    } else {
        // comb branch: prefetch first half of row BEFORE the wait.
        const int r = (blockIdx.x - 768) * 8 + warp;      // 0..2047
        const float4* w = reinterpret_cast<const float4*>(comb_w) + (long long)r * 1024;

        float4 wreg[16];
        #pragma unroll
        for (int j = 0; j < 16; j++)
            wreg[j] = __ldcs(w + lane + 32 * j);          // i in [0, 512)

        GDC_WAIT();                                       // g_concat from k1b
        for (int i = tid; i < 1024; i += 256)
            xs[i] = reinterpret_cast<const float4*>(g_concat)[i];
        __syncthreads();

        float s = 0.f;
        #pragma unroll
        for (int j = 0; j < 16; j++)
            s += dot4(wreg[j], xs[lane + 32 * j]);
        #pragma unroll 8
        for (int i = 512 + lane; i < 1024; i += 32)
            s += dot4(__ldcs(w + i), xs[i]);
        s = warp_reduce(s);
        if (lane == 0) g_x[r] = fmaxf(s + comb_b[r], 0.f);
    }
}

// ---------------------------------------------------------------------------
// K3: gi GEMV + GRU gates. block = 192 (6 warps = 2 k's x 3 gates),
// grid = 1024. Each warp prefetches its FULL 2KB w_ih row into 16 float4
// registers BEFORE waiting on k2 -> w_ih streams during k2's tail.
// ---------------------------------------------------------------------------
__global__ void __launch_bounds__(192) k3_gru(
    const float* __restrict__ w_ih, const float* __restrict__ b_ih,
    const float* __restrict__ hidden, float* __restrict__ out)
{
    GDC_LAUNCH();
    __shared__ float4 xs[512];
    __shared__ float s_gi[2][3];
    const int tid  = threadIdx.x;
    const int warp = tid >> 5;
    const int lane = tid & 31;

    const int kl   = warp / 3;            // 0..1
    const int gate = warp - kl * 3;       // 0..2
    const int k    = blockIdx.x * 2 + kl;
    const int row  = k + gate * H;

    const float4* w = reinterpret_cast<const float4*>(w_ih) + (long long)row * 512;
    float4 wreg[16];
    #pragma unroll
    for (int j = 0; j < 16; j++)
        wreg[j] = __ldcs(w + lane + 32 * j);

    GDC_WAIT();                           // g_x + g_gh from k2
    for (int i = tid; i < 512; i += 192)
        xs[i] = reinterpret_cast<const float4*>(g_x)[i];
    __syncthreads();

    float s = 0.f;
    #pragma unroll
    for (int j = 0; j < 16; j++)
        s += dot4(wreg[j], xs[lane + 32 * j]);
    s = warp_reduce(s);
    if (lane == 0) s_gi[kl][gate] = s + b_ih[row];
    __syncthreads();

    if (tid < 2) {
        const int kk = blockIdx.x * 2 + tid;
        float i_r = s_gi[tid][0], i_z = s_gi[tid][1], i_n = s_gi[tid][2];
        float h_r = g_gh[kk], h_z = g_gh[kk + H], h_n = g_gh[kk + 2 * H];
        float rr = 1.f / (1.f + __expf(-(i_r + h_r)));
        float zz = 1.f / (1.f + __expf(-(i_z + h_z)));
        float nn = tanhf(i_n + rr * h_n);
        float h0 = hidden[kk];
        float hn = (1.f - zz) * nn + zz * h0;
        g_hnew[kk]  = hn;
        out[V + kk] = hn;
    }
}

// ---------------------------------------------------------------------------
// K4: logits = out_w @ h_new + out_b. One row per warp; each warp prefetches
// its FULL 2KB out_w row into 16 float4 registers BEFORE waiting on k3 ->
// the first resident wave streams out_w concurrently with k3.
// grid = ceil(V/8), block = 256.
// ---------------------------------------------------------------------------
__global__ void __launch_bounds__(256) k4_logits(
    const float* __restrict__ out_w, const float* __restrict__ out_b,
    float* __restrict__ out)
{
    __shared__ float4 xs[512];
    const int tid  = threadIdx.x;
    const int warp = tid >> 5;
    const int lane = tid & 31;

    const long long r = (long long)blockIdx.x * 8 + warp;
    const bool valid = (r < V);

    float4 wreg[16];
    if (valid) {
        const float4* w = reinterpret_cast<const float4*>(out_w) + r * 512;
        #pragma unroll
        for (int j = 0; j < 16; j++)
            wreg[j] = __ldcs(w + lane + 32 * j);
    }

    GDC_WAIT();                           // g_hnew from k3
    for (int i = tid; i < 512; i += 256)
        xs[i] = reinterpret_cast<const float4*>(g_hnew)[i];
    __syncthreads();

    if (!valid) return;
    float s = 0.f;
    #pragma unroll
    for (int j = 0; j < 16; j++)
        s += dot4(wreg[j], xs[lane + 32 * j]);
    s = warp_reduce(s);
    if (lane == 0) out[r] = s + out_b[r];
}

// ---------------------------------------------------------------------------
extern "C" void kernel_launch(void* const* d_in, const int* in_sizes, int n_in,
                              void* d_out, int out_size)
{
    const int*   input_ids = (const int*)  d_in[0];
    const float* hidden    = (const float*)d_in[1];
    const float* enc       = (const float*)d_in[2];
    const float* emb       = (const float*)d_in[3];
    const float* attn_w    = (const float*)d_in[4];
    const float* attn_b    = (const float*)d_in[5];
    const float* comb_w    = (const float*)d_in[6];
    const float* comb_b    = (const float*)d_in[7];
    const float* w_ih      = (const float*)d_in[8];
    const float* w_hh      = (const float*)d_in[9];
    const float* b_ih      = (const float*)d_in[10];
    const float* b_hh      = (const float*)d_in[11];
    const float* out_w     = (const float*)d_in[12];
    const float* out_b     = (const float*)d_in[13];
    float* out = (float*)d_out;

    // First kernel: plain launch.
    k1a_scores<<<L, 256>>>(input_ids, hidden, emb, attn_w, attn_b);

    // Subsequent kernels: programmatic stream serialization (PDL).
    cudaLaunchAttribute attr[1];
    attr[0].id = cudaLaunchAttributeProgrammaticStreamSerialization;
    attr[0].val.programmaticStreamSerializationAllowed = 1;

    {
        cudaLaunchConfig_t cfg = {};
        cfg.gridDim = dim3(16); cfg.blockDim = dim3(128);
        cfg.attrs = attr; cfg.numAttrs = 1; cfg.stream = 0;
        cudaLaunchKernelEx(&cfg, k1b_ctx, input_ids, enc, emb, out);
    }
    {
        cudaLaunchConfig_t cfg = {};
        cfg.gridDim = dim3(1024); cfg.blockDim = dim3(256);
        cfg.attrs = attr; cfg.numAttrs = 1; cfg.stream = 0;
        cudaLaunchKernelEx(&cfg, k2_comb_gh, comb_w, comb_b, w_hh, b_hh, hidden);
    }
    {
        cudaLaunchConfig_t cfg = {};
        cfg.gridDim = dim3(1024); cfg.blockDim = dim3(192);
        cfg.attrs = attr; cfg.numAttrs = 1; cfg.stream = 0;
        cudaLaunchKernelEx(&cfg, k3_gru, w_ih, b_ih, hidden, out);
    }
    {
        cudaLaunchConfig_t cfg = {};
        cfg.gridDim = dim3((V + 7) / 8); cfg.blockDim = dim3(256);
        cfg.attrs = attr; cfg.numAttrs = 1; cfg.stream = 0;
        cudaLaunchKernelEx(&cfg, k4_logits, out_w, out_b, out);
    }
}

// round 15
// speedup vs baseline: 1.1622x; 1.0273x over previous
#include <cuda_runtime.h>
#include <math.h>

#define H 2048
#define V 50257
#define L 20

// Programmatic dependent launch controls (sm_90+)
#define GDC_LAUNCH() asm volatile("griddepcontrol.launch_dependents;")
#define GDC_WAIT()   asm volatile("griddepcontrol.wait;" ::: "memory")

// Scratch (device globals: no allocation allowed in kernel_launch)
__device__ __align__(16) float g_sc[L];           // raw attention scores
__device__ __align__(16) float g_concat[2 * H];   // [embedded ; context]
__device__ __align__(16) float g_x[H];            // relu(comb) output
__device__ __align__(16) float g_gh[3 * H];       // w_hh @ h0 + b_hh
__device__ __align__(16) float g_hnew[H];         // new hidden

// Self-resetting sync counters for k1 (return to 0 by end of each launch).
__device__ int c_sc  = 0;     // score blocks done (target 20)
__device__ int c_fin = 0;     // ctx blocks finished (target 8; last one resets)

__device__ __forceinline__ float warp_reduce(float v) {
    #pragma unroll
    for (int o = 16; o > 0; o >>= 1)
        v += __shfl_xor_sync(0xFFFFFFFFu, v, o);
    return v;
}

__device__ __forceinline__ float dot4(float4 a, float4 b) {
    return a.x * b.x + a.y * b.y + a.z * b.z + a.w * b.w;
}

// ---------------------------------------------------------------------------
// K1: fused attention. Blocks 0..19: one score each. Blocks 20..27: softmax
// (redundant) + context + concat (256 j's each), spin on score counter.
// All blocks GDC_LAUNCH at entry -> k2's gh stream starts at k1's START.
// ---------------------------------------------------------------------------
__global__ void __launch_bounds__(256) k1_fused(
    const int* __restrict__ input_ids,
    const float* __restrict__ hidden,
    const float* __restrict__ emb,
    const float* __restrict__ attn_w,
    const float* __restrict__ attn_b,
    const float* __restrict__ enc,
    float* __restrict__ out)
{
    GDC_LAUNCH();
    const int bid = blockIdx.x;
    const int tid = threadIdx.x;
    const int id  = input_ids[0];

    if (bid < L) {
        // ---- score block: s[bid] = attn_w[bid] . [emb_row ; h0] + b ----
        __shared__ float red[8];
        const float4* aw = reinterpret_cast<const float4*>(attn_w + bid * (2 * H));
        const float4* e4 = reinterpret_cast<const float4*>(emb + (long long)id * H);
        const float4* h4 = reinterpret_cast<const float4*>(hidden);

        float s = 0.f;
        #pragma unroll
        for (int i = tid; i < 1024; i += 256) {
            float4 a = __ldcs(aw + i);
            float4 x = (i < 512) ? e4[i] : h4[i - 512];
            s += dot4(a, x);
        }
        s = warp_reduce(s);
        if ((tid & 31) == 0) red[tid >> 5] = s;
        __syncthreads();
        if (tid < 8) {
            float v = red[tid];
            #pragma unroll
            for (int o = 4; o > 0; o >>= 1) v += __shfl_xor_sync(0xFFu, v, o);
            if (tid == 0) {
                g_sc[bid] = v + attn_b[bid];
                __threadfence();
                atomicAdd(&c_sc, 1);
            }
        }
    } else {
        // ---- ctx block: wait for all 20 scores, then context + concat ----
        __shared__ float sw[L];
        if (tid == 0) {
            while (atomicAdd(&c_sc, 0) < L) __nanosleep(64);
        }
        __syncthreads();
        __threadfence();

        if (tid == 0) {
            float m = g_sc[0];
            #pragma unroll
            for (int l = 1; l < L; l++) m = fmaxf(m, g_sc[l]);
            float ssum = 0.f;
            float e[L];
            #pragma unroll
            for (int l = 0; l < L; l++) { e[l] = __expf(g_sc[l] - m); ssum += e[l]; }
            float inv = 1.f / ssum;
            #pragma unroll
            for (int l = 0; l < L; l++) sw[l] = e[l] * inv;
        }
        __syncthreads();

        const int j = (bid - L) * 256 + tid;      // 0..2047
        float ctx = 0.f;
        #pragma unroll
        for (int l = 0; l < L; l++)
            ctx += sw[l] * enc[l * H + j];

        g_concat[j]     = emb[(long long)id * H + j];
        g_concat[H + j] = ctx;

        if (bid == L && tid < L) out[V + H + tid] = sw[tid];

        __syncthreads();
        if (tid == 0) {
            int f = atomicAdd(&c_fin, 1);
            if (f == 7) {                          // last ctx block: reset
                atomicExch(&c_sc, 0);
                atomicExch(&c_fin, 0);
            }
        }
    }
}

// ---------------------------------------------------------------------------
// K2: gh GEMV in blocks 0..767 (NO dependency -> streams from k1's start),
//     comb GEMV in blocks 768..1023 (prefetch half row, then wait on k1).
// ---------------------------------------------------------------------------
__global__ void __launch_bounds__(256) k2_comb_gh(
    const float* __restrict__ comb_w, const float* __restrict__ comb_b,
    const float* __restrict__ w_hh,   const float* __restrict__ b_hh,
    const float* __restrict__ hidden)
{
    GDC_LAUNCH();
    __shared__ float4 xs[1024];
    const int tid  = threadIdx.x;
    const int warp = tid >> 5;
    const int lane = tid & 31;

    if (blockIdx.x < 768) {
        for (int i = tid; i < 512; i += 256)
            xs[i] = reinterpret_cast<const float4*>(hidden)[i];
        __syncthreads();

        const int r = blockIdx.x * 8 + warp;              // 0..6143
        const float4* w = reinterpret_cast<const float4*>(w_hh) + (long long)r * 512;
        float s = 0.f;
        #pragma unroll 8
        for (int i = lane; i < 512; i += 32)
            s += dot4(__ldcs(w + i), xs[i]);
        s = warp_reduce(s);
        if (lane == 0) g_gh[r] = s + b_hh[r];
    } else {
        const int r = (blockIdx.x - 768) * 8 + warp;      // 0..2047
        const float4* w = reinterpret_cast<const float4*>(comb_w) + (long long)r * 1024;

        float4 wreg[16];
        #pragma unroll
        for (int j = 0; j < 16; j++)
            wreg[j] = __ldcs(w + lane + 32 * j);          // i in [0, 512)

        GDC_WAIT();                                       // g_concat from k1
        for (int i = tid; i < 1024; i += 256)
            xs[i] = reinterpret_cast<const float4*>(g_concat)[i];
        __syncthreads();

        float s = 0.f;
        #pragma unroll
        for (int j = 0; j < 16; j++)
            s += dot4(wreg[j], xs[lane + 32 * j]);
        #pragma unroll 8
        for (int i = 512 + lane; i < 1024; i += 32)
            s += dot4(__ldcs(w + i), xs[i]);
        s = warp_reduce(s);
        if (lane == 0) g_x[r] = fmaxf(s + comb_b[r], 0.f);
    }
}

// ---------------------------------------------------------------------------
// K3: gi GEMV + GRU gates. block = 384 (12 warps = 4 k's x 3 gates, no
// waste), grid = 512. Half-row prefetch (8 float4 = 32 regs) before wait
// keeps ~56 regs -> 3 CTAs/SM, 36 streaming warps/SM.
// ---------------------------------------------------------------------------
__global__ void __launch_bounds__(384) k3_gru(
    const float* __restrict__ w_ih, const float* __restrict__ b_ih,
    const float* __restrict__ hidden, float* __restrict__ out)
{
    GDC_LAUNCH();
    __shared__ float4 xs[512];
    __shared__ float s_gi[4][3];
    const int tid  = threadIdx.x;
    const int warp = tid >> 5;
    const int lane = tid & 31;

    const int kl   = warp / 3;            // 0..3
    const int gate = warp - kl * 3;       // 0..2
    const int k    = blockIdx.x * 4 + kl;
    const int row  = k + gate * H;

    const float4* w = reinterpret_cast<const float4*>(w_ih) + (long long)row * 512;
    float4 wreg[8];
    #pragma unroll
    for (int j = 0; j < 8; j++)
        wreg[j] = __ldcs(w + lane + 32 * j);  // first half of the row

    GDC_WAIT();                           // g_x + g_gh from k2
    for (int i = tid; i < 512; i += 384)
        xs[i] = reinterpret_cast<const float4*>(g_x)[i];
    __syncthreads();

    float s = 0.f;
    #pragma unroll
    for (int j = 0; j < 8; j++)
        s += dot4(wreg[j], xs[lane + 32 * j]);
    #pragma unroll 8
    for (int i = 256 + lane; i < 512; i += 32)
        s += dot4(__ldcs(w + i), xs[i]);
    s = warp_reduce(s);
    if (lane == 0) s_gi[kl][gate] = s + b_ih[row];
    __syncthreads();

    if (tid < 4) {
        const int kk = blockIdx.x * 4 + tid;
        float i_r = s_gi[tid][0], i_z = s_gi[tid][1], i_n = s_gi[tid][2];
        float h_r = g_gh[kk], h_z = g_gh[kk + H], h_n = g_gh[kk + 2 * H];
        float rr = 1.f / (1.f + __expf(-(i_r + h_r)));
        float zz = 1.f / (1.f + __expf(-(i_z + h_z)));
        float nn = tanhf(i_n + rr * h_n);
        float h0 = hidden[kk];
        float hn = (1.f - zz) * nn + zz * h0;
        g_hnew[kk]  = hn;
        out[V + kk] = hn;
    }
}

// ---------------------------------------------------------------------------
// K4: logits = out_w @ h_new + out_b. One row per warp; full-row register
// prefetch before the wait (first resident wave streams during k3).
// grid = ceil(V/8), block = 256.
// ---------------------------------------------------------------------------
__global__ void __launch_bounds__(256) k4_logits(
    const float* __restrict__ out_w, const float* __restrict__ out_b,
    float* __restrict__ out)
{
    __shared__ float4 xs[512];
    const int tid  = threadIdx.x;
    const int warp = tid >> 5;
    const int lane = tid & 31;

    const long long r = (long long)blockIdx.x * 8 + warp;
    const bool valid = (r < V);

    float4 wreg[16];
    if (valid) {
        const float4* w = reinterpret_cast<const float4*>(out_w) + r * 512;
        #pragma unroll
        for (int j = 0; j < 16; j++)
            wreg[j] = __ldcs(w + lane + 32 * j);
    }

    GDC_WAIT();                           // g_hnew from k3
    for (int i = tid; i < 512; i += 256)
        xs[i] = reinterpret_cast<const float4*>(g_hnew)[i];
    __syncthreads();

    if (!valid) return;
    float s = 0.f;
    #pragma unroll
    for (int j = 0; j < 16; j++)
        s += dot4(wreg[j], xs[lane + 32 * j]);
    s = warp_reduce(s);
    if (lane == 0) out[r] = s + out_b[r];
}

// ---------------------------------------------------------------------------
extern "C" void kernel_launch(void* const* d_in, const int* in_sizes, int n_in,
                              void* d_out, int out_size)
{
    const int*   input_ids = (const int*)  d_in[0];
    const float* hidden    = (const float*)d_in[1];
    const float* enc       = (const float*)d_in[2];
    const float* emb       = (const float*)d_in[3];
    const float* attn_w    = (const float*)d_in[4];
    const float* attn_b    = (const float*)d_in[5];
    const float* comb_w    = (const float*)d_in[6];
    const float* comb_b    = (const float*)d_in[7];
    const float* w_ih      = (const float*)d_in[8];
    const float* w_hh      = (const float*)d_in[9];
    const float* b_ih      = (const float*)d_in[10];
    const float* b_hh      = (const float*)d_in[11];
    const float* out_w     = (const float*)d_in[12];
    const float* out_b     = (const float*)d_in[13];
    float* out = (float*)d_out;

    // First kernel: plain launch (fused scores + softmax + context).
    k1_fused<<<L + 8, 256>>>(input_ids, hidden, emb, attn_w, attn_b, enc, out);

    // Subsequent kernels: programmatic stream serialization (PDL).
    cudaLaunchAttribute attr[1];
    attr[0].id = cudaLaunchAttributeProgrammaticStreamSerialization;
    attr[0].val.programmaticStreamSerializationAllowed = 1;

    {
        cudaLaunchConfig_t cfg = {};
        cfg.gridDim = dim3(1024); cfg.blockDim = dim3(256);
        cfg.attrs = attr; cfg.numAttrs = 1; cfg.stream = 0;
        cudaLaunchKernelEx(&cfg, k2_comb_gh, comb_w, comb_b, w_hh, b_hh, hidden);
    }
    {
        cudaLaunchConfig_t cfg = {};
        cfg.gridDim = dim3(512); cfg.blockDim = dim3(384);
        cfg.attrs = attr; cfg.numAttrs = 1; cfg.stream = 0;
        cudaLaunchKernelEx(&cfg, k3_gru, w_ih, b_ih, hidden, out);
    }
    {
        cudaLaunchConfig_t cfg = {};
        cfg.gridDim = dim3((V + 7) / 8); cfg.blockDim = dim3(256);
        cfg.attrs = attr; cfg.numAttrs = 1; cfg.stream = 0;
        cudaLaunchKernelEx(&cfg, k4_logits, out_w, out_b, out);
    }
}